// round 16
// baseline (speedup 1.0000x reference)
#include <cuda_runtime.h>
#include <cuda.h>
#include <cuda_fp16.h>
#include <cstdint>

// ============================================================================
// SpikingLinearLayer — fp16 2-plane GEMM with FUSED LIF scan epilogue
//   x is converted into permuted layout [b*20+t, IN] so one 160-row m-tile
//   holds 8 complete neurons' t-chains; the GEMM epilogue folds both planes,
//   stages c in smem, runs the 20-step LIF scan, and writes spikes directly.
//   No intermediate current buffer, no separate scan kernel.
// ============================================================================

namespace {

constexpr int T_STEPS = 20;
constexpr int BATCH   = 1024;
constexpr int IN_DIM  = 2048;
constexpr int OUT_DIM = 2048;
constexpr int M_TOTAL = T_STEPS * BATCH;     // 20480
constexpr int K_CAT   = 2 * IN_DIM;          // 4096

constexpr float ALPHA_S = 0.8f;
constexpr float ALPHA_M = 0.95f;
constexpr float DT_TAUM = 0.05f;
constexpr float P1_SCALE    = 1024.0f;
constexpr float P1_INVSCALE = 0.0009765625f;   // 2^-10

__device__ __align__(1024) __half g_x_f16[(size_t)M_TOTAL * IN_DIM];   // permuted [b*20+t, k]
__device__ __align__(1024) __half g_w_cat[(size_t)OUT_DIM * K_CAT];

__device__ __forceinline__ uint32_t smem_u32(const void* p) {
    uint32_t a;
    asm("{ .reg .u64 t; cvta.to.shared.u64 t, %1; cvt.u32.u64 %0, t; }"
        : "=r"(a) : "l"(p));
    return a;
}

#define MBAR_INIT(addr, cnt) \
    asm volatile("mbarrier.init.shared.b64 [%0], %1;" :: "r"(addr), "r"(cnt) : "memory")
#define MBAR_ARRIVE(addr) \
    asm volatile("mbarrier.arrive.shared.b64 _, [%0];" :: "r"(addr) : "memory")
#define MBAR_EXPECT_TX(addr, bytes) \
    asm volatile("mbarrier.arrive.expect_tx.shared.b64 _, [%0], %1;" \
        :: "r"(addr), "r"(bytes) : "memory")
#define MBAR_WAIT(addr, ph) do {                                                   \
    uint32_t _m = (addr), _p = (ph), _d;                                           \
    asm volatile("{\n\t.reg .pred p;\n\t"                                          \
        "mbarrier.try_wait.parity.acquire.cta.shared::cta.b64 p, [%1], %2;\n\t"    \
        "selp.b32 %0, 1, 0, p;\n\t}" : "=r"(_d) : "r"(_m), "r"(_p) : "memory");    \
    if (!_d) {                                                                     \
        asm volatile("{\n\t.reg .pred P;\n\t"                                      \
        "WL_%=:\n\t"                                                               \
        "mbarrier.try_wait.parity.acquire.cta.shared::cta.b64 P, [%0], %1, 0x989680;\n\t" \
        "@P bra.uni WD_%=;\n\t"                                                    \
        "bra.uni WL_%=;\n\t"                                                       \
        "WD_%=:\n\t}" :: "r"(_m), "r"(_p) : "memory");                             \
    }                                                                              \
} while (0)

#define TMA_LOAD_2D(dst, map_addr, c0, c1, mbar) \
    asm volatile( \
        "cp.async.bulk.tensor.2d.shared::cta.global.tile.mbarrier::complete_tx::bytes " \
        "[%0], [%1, {%2, %3}], [%4];" \
        :: "r"(dst), "l"(map_addr), "r"(c0), "r"(c1), "r"(mbar) : "memory")

__device__ __forceinline__ void ldsm4(uint32_t& r0, uint32_t& r1, uint32_t& r2,
                                      uint32_t& r3, uint32_t addr) {
    asm volatile("ldmatrix.sync.aligned.m8n8.x4.shared.b16 {%0,%1,%2,%3}, [%4];"
                 : "=r"(r0), "=r"(r1), "=r"(r2), "=r"(r3) : "r"(addr));
}

__device__ __forceinline__ void mma16816(float* d, uint32_t a0, uint32_t a1,
                                         uint32_t a2, uint32_t a3,
                                         uint32_t b0, uint32_t b1) {
    asm volatile(
        "mma.sync.aligned.m16n8k16.row.col.f32.f16.f16.f32 "
        "{%0,%1,%2,%3}, {%4,%5,%6,%7}, {%8,%9}, {%0,%1,%2,%3};"
        : "+f"(d[0]), "+f"(d[1]), "+f"(d[2]), "+f"(d[3])
        : "r"(a0), "r"(a1), "r"(a2), "r"(a3), "r"(b0), "r"(b1));
}

__device__ __forceinline__ void mma16816_h(uint32_t* d, uint32_t a0, uint32_t a1,
                                           uint32_t a2, uint32_t a3,
                                           uint32_t b0, uint32_t b1) {
    asm volatile(
        "mma.sync.aligned.m16n8k16.row.col.f16.f16.f16.f16 "
        "{%0,%1}, {%2,%3,%4,%5}, {%6,%7}, {%0,%1};"
        : "+r"(d[0]), "+r"(d[1])
        : "r"(a0), "r"(a1), "r"(a2), "r"(a3), "r"(b0), "r"(b1));
}

// ============================================================================
// Converts: x fp32 [t,b,k] -> fp16 permuted [b*20+t, k] ; w -> 2 fp16 planes
// ============================================================================
constexpr int XBLKS = (int)((size_t)M_TOTAL * IN_DIM / 4 / 256);  // 40960
constexpr int WBLKS = (int)((size_t)OUT_DIM * IN_DIM / 4 / 256);  // 4096

__global__ void convert_all_kernel(const float* __restrict__ x,
                                   const float* __restrict__ w) {
    const int bid = blockIdx.x;
    if (bid < XBLKS) {
        size_t i = ((size_t)bid * blockDim.x + threadIdx.x) * 4;
        int rowp = (int)(i / IN_DIM);          // b*20 + t
        int k    = (int)(i % IN_DIM);
        int b = rowp / T_STEPS;
        int t = rowp - b * T_STEPS;
        const float* src = x + ((size_t)t * BATCH + b) * IN_DIM + k;
        float4 v = *reinterpret_cast<const float4*>(src);
        __half2 lo = __floats2half2_rn(v.x, v.y);
        __half2 hi = __floats2half2_rn(v.z, v.w);
        uint2 packed = make_uint2(*reinterpret_cast<uint32_t*>(&lo),
                                  *reinterpret_cast<uint32_t*>(&hi));
        *reinterpret_cast<uint2*>(g_x_f16 + i) = packed;
    } else {
        size_t i = ((size_t)(bid - XBLKS) * blockDim.x + threadIdx.x) * 4;
        int o = (int)(i / IN_DIM);
        int k = (int)(i % IN_DIM);
        float4 v = *reinterpret_cast<const float4*>(w + i);
        float vv[4] = {v.x, v.y, v.z, v.w};
        __half p0[4], p1[4];
#pragma unroll
        for (int j = 0; j < 4; j++) {
            float f = vv[j];
            __half h0 = __float2half_rn(f);
            float r1 = f - __half2float(h0);
            p0[j] = h0;
            p1[j] = __float2half_rn(r1 * P1_SCALE);
        }
        __half* base = g_w_cat + (size_t)o * K_CAT + k;
        *reinterpret_cast<uint2*>(base)          = *reinterpret_cast<uint2*>(p0);
        *reinterpret_cast<uint2*>(base + IN_DIM) = *reinterpret_cast<uint2*>(p1);
    }
}

// ============================================================================
// Fused GEMM + LIF:  c = X*W0^T + 2^-10 X*W1'^T ; scan over t ; emit spikes
//   CTA 160(M: 8 batches x 20 t) x 128(N); 8 warps @ 80x32; BK=64; 2-stage TMA.
// ============================================================================
constexpr int TILE_M = 160;
constexpr int TILE_N = 128;
constexpr int BK     = 64;
constexpr int NTH    = 256;
constexpr int KITERS = IN_DIM / BK;        // 32
constexpr int MT     = 5;                  // m16 tiles per warp (80 rows)

constexpr int A_BYTES  = TILE_M * BK * 2;  // 20480
constexpr int B_BYTES  = TILE_N * BK * 2;  // 16384 per plane
constexpr int STAGE_BYTES = A_BYTES + 2 * B_BYTES;   // 53248
constexpr int SMEM_BYTES  = 2048 + 2 * STAGE_BYTES;  // 108544

constexpr int CS_STRIDE = TILE_N + 4;      // 132 floats, pad vs bank conflicts

__global__ void __launch_bounds__(NTH, 1)
snn_fused_kernel(const __grid_constant__ CUtensorMap tma_a,
                 const __grid_constant__ CUtensorMap tma_b,
                 float* __restrict__ out) {
    extern __shared__ char smem_raw[];
    const uint32_t raw = smem_u32(smem_raw);
    const uint32_t sbase = (raw + 1023) & ~1023u;
    const uint32_t stg_base = sbase + 1024;
    float* cs = reinterpret_cast<float*>(smem_raw + (stg_base - raw));

    const int tid  = threadIdx.x;
    const int lane = tid & 31;
    const int wid  = tid >> 5;
    const int mw   = wid & 1;        // 0..1 -> 80-row band
    const int nwp  = wid >> 1;       // 0..3 -> 32-col band
    const int bid  = blockIdx.x;
    const int m0   = (bid >> 4) * TILE_M;   // 128 m-tiles
    const int n0   = (bid & 15) * TILE_N;   // 16 n-blocks (W stays in L2)
    const int b0   = (bid >> 4) * 8;        // first batch of this tile

    if (tid == 0) {
#pragma unroll
        for (int s = 0; s < 2; s++) {
            MBAR_INIT(sbase + s * 8, 1);         // full: tx-based
            MBAR_INIT(sbase + 16 + s * 8, NTH);  // empty: all threads arrive
        }
    }
    __syncthreads();

    const uint64_t map_a = (uint64_t)&tma_a;
    const uint64_t map_b = (uint64_t)&tma_b;

    auto load_stage = [&](int kc) {
        const int s = kc & 1;
        const uint32_t stg = stg_base + s * STAGE_BYTES;
        const uint32_t mb = sbase + s * 8;
        MBAR_EXPECT_TX(mb, STAGE_BYTES);
        TMA_LOAD_2D(stg,                     map_a, kc * BK,           m0, mb);
        TMA_LOAD_2D(stg + A_BYTES,           map_b, kc * BK,           n0, mb);
        TMA_LOAD_2D(stg + A_BYTES + B_BYTES, map_b, IN_DIM + kc * BK,  n0, mb);
    };

    if (tid == 0) { load_stage(0); load_stage(1); }

    const int lr = lane & 15;
    const int halfsel = (lane >> 4) * 16;
    uint32_t a_rowoff[MT], a_xr[MT];
#pragma unroll
    for (int mt = 0; mt < MT; mt++) {
        int r = mw * 80 + mt * 16 + lr;       // 0..159
        a_rowoff[mt] = r * 128;
        a_xr[mt] = (r & 7) * 16;
    }
    uint32_t b_rowoff[2], b_xr[2];
#pragma unroll
    for (int nt = 0; nt < 2; nt++) {
        int r = nwp * 32 + nt * 16 + lr;      // 0..127
        b_rowoff[nt] = r * 128;
        b_xr[nt] = (r & 7) * 16;
    }

    float acc0[MT][4][4];          // [mt][n8][4] plane0 fp32
    uint32_t acc1[MT][4][2];       // [mt][n8][2] plane1 fp16x2
#pragma unroll
    for (int i = 0; i < MT; i++)
#pragma unroll
        for (int j = 0; j < 4; j++) {
#pragma unroll
            for (int q = 0; q < 4; q++) acc0[i][j][q] = 0.0f;
            acc1[i][j][0] = 0u; acc1[i][j][1] = 0u;
        }

    int pf[2] = {0, 0}, pe[2] = {0, 0};

    for (int kc = 0; kc < KITERS; kc++) {
        const int s = kc & 1;
        const uint32_t stg = stg_base + s * STAGE_BYTES;
        MBAR_WAIT(sbase + s * 8, pf[s]);
        pf[s] ^= 1;

#pragma unroll
        for (int kk = 0; kk < 4; kk++) {
            const uint32_t kb = kk * 32 + halfsel;
            uint32_t a[MT][4];
#pragma unroll
            for (int mt = 0; mt < MT; mt++)
                ldsm4(a[mt][0], a[mt][1], a[mt][2], a[mt][3],
                      stg + a_rowoff[mt] + (kb ^ a_xr[mt]));

            // ---- plane 0 (fp32 acc) ----
#pragma unroll
            for (int nt = 0; nt < 2; nt++) {
                uint32_t b0r, b1r, b2r, b3r;
                ldsm4(b0r, b1r, b2r, b3r,
                      stg + A_BYTES + b_rowoff[nt] + (kb ^ b_xr[nt]));
#pragma unroll
                for (int mt = 0; mt < MT; mt++) {
                    mma16816(acc0[mt][nt * 2 + 0], a[mt][0], a[mt][1],
                             a[mt][2], a[mt][3], b0r, b2r);
                    mma16816(acc0[mt][nt * 2 + 1], a[mt][0], a[mt][1],
                             a[mt][2], a[mt][3], b1r, b3r);
                }
            }
            // ---- plane 1 (scaled residual, fp16 acc) ----
#pragma unroll
            for (int nt = 0; nt < 2; nt++) {
                uint32_t b0r, b1r, b2r, b3r;
                ldsm4(b0r, b1r, b2r, b3r,
                      stg + A_BYTES + B_BYTES + b_rowoff[nt] + (kb ^ b_xr[nt]));
#pragma unroll
                for (int mt = 0; mt < MT; mt++) {
                    mma16816_h(acc1[mt][nt * 2 + 0], a[mt][0], a[mt][1],
                               a[mt][2], a[mt][3], b0r, b2r);
                    mma16816_h(acc1[mt][nt * 2 + 1], a[mt][0], a[mt][1],
                               a[mt][2], a[mt][3], b1r, b3r);
                }
            }
        }

        MBAR_ARRIVE(sbase + 16 + s * 8);
        if (tid == 0 && kc + 2 < KITERS) {
            MBAR_WAIT(sbase + 16 + s * 8, pe[s]);
            pe[s] ^= 1;
            load_stage(kc + 2);
        }
    }

    // ---- epilogue 1: fold planes, stage c-tile in smem (alias stage bufs) ----
    __syncthreads();   // all warps done reading stage smem

    const int srow = mw * 80 + (lane >> 2);
    const int scol = nwp * 32 + (lane & 3) * 2;
#pragma unroll
    for (int mt = 0; mt < MT; mt++) {
        float* c0p = cs + (srow + mt * 16) * CS_STRIDE + scol;
        float* c1p = c0p + 8 * CS_STRIDE;
#pragma unroll
        for (int j = 0; j < 4; j++) {
            float2 lo = __half22float2(
                *reinterpret_cast<const __half2*>(&acc1[mt][j][0]));
            float2 hi = __half22float2(
                *reinterpret_cast<const __half2*>(&acc1[mt][j][1]));
            c0p[j * 8 + 0] = fmaf(lo.x, P1_INVSCALE, acc0[mt][j][0]);
            c0p[j * 8 + 1] = fmaf(lo.y, P1_INVSCALE, acc0[mt][j][1]);
            c1p[j * 8 + 0] = fmaf(hi.x, P1_INVSCALE, acc0[mt][j][2]);
            c1p[j * 8 + 1] = fmaf(hi.y, P1_INVSCALE, acc0[mt][j][3]);
        }
    }
    __syncthreads();

    // ---- epilogue 2: LIF scan over t for 4 neurons per thread ----
#pragma unroll
    for (int q = 0; q < 4; q++) {
        const int n = tid + q * 256;          // 0..1023
        const int b_loc = n >> 7;             // 0..7
        const int o_loc = n & 127;
        const float* crow = cs + (b_loc * T_STEPS) * CS_STRIDE + o_loc;
        float* orow = out + (size_t)(b0 + b_loc) * OUT_DIM + n0 + o_loc;
        float V = 0.0f, I = 0.0f;
#pragma unroll
        for (int t = 0; t < T_STEPS; t++) {
            float c = crow[t * CS_STRIDE];
            I = ALPHA_S * I + c;
            V = ALPHA_M * V + DT_TAUM * I;
            float s = (V >= 1.0f) ? 1.0f : 0.0f;
            V *= (1.0f - s);
            __stcs(orow + (size_t)t * BATCH * OUT_DIM, s);
        }
    }
}

}  // namespace

// ---- host-side tensormap setup (rebuilt every call; no static guards) ----
typedef CUresult (*PFN_cuTensorMapEncodeTiled)(
    CUtensorMap*, CUtensorMapDataType, cuuint32_t, void*,
    const cuuint64_t*, const cuuint64_t*, const cuuint32_t*, const cuuint32_t*,
    CUtensorMapInterleave, CUtensorMapSwizzle, CUtensorMapL2promotion,
    CUtensorMapFloatOOBfill);

static CUtensorMap s_tma_a, s_tma_b;

static void build_tensormaps() {
    PFN_cuTensorMapEncodeTiled encode = nullptr;
    cudaDriverEntryPointQueryResult qres;
    cudaGetDriverEntryPoint("cuTensorMapEncodeTiled", (void**)&encode,
                            cudaEnableDefault, &qres);
    if (!encode) return;
    void* xa; cudaGetSymbolAddress(&xa, g_x_f16);
    void* wa; cudaGetSymbolAddress(&wa, g_w_cat);

    {   // A: [2048 x 20480] fp16 (permuted rows), box [64 x 160]
        cuuint64_t dims[2]    = {(cuuint64_t)IN_DIM, (cuuint64_t)M_TOTAL};
        cuuint64_t strides[1] = {(cuuint64_t)IN_DIM * 2};
        cuuint32_t box[2]     = {BK, TILE_M};
        cuuint32_t es[2]      = {1, 1};
        encode(&s_tma_a, CU_TENSOR_MAP_DATA_TYPE_FLOAT16, 2, xa,
               dims, strides, box, es,
               CU_TENSOR_MAP_INTERLEAVE_NONE, CU_TENSOR_MAP_SWIZZLE_128B,
               CU_TENSOR_MAP_L2_PROMOTION_L2_128B,
               CU_TENSOR_MAP_FLOAT_OOB_FILL_NONE);
    }
    {   // B: [4096 x 2048] fp16, box [64 x 128]
        cuuint64_t dims[2]    = {(cuuint64_t)K_CAT, (cuuint64_t)OUT_DIM};
        cuuint64_t strides[1] = {(cuuint64_t)K_CAT * 2};
        cuuint32_t box[2]     = {BK, TILE_N};
        cuuint32_t es[2]      = {1, 1};
        encode(&s_tma_b, CU_TENSOR_MAP_DATA_TYPE_FLOAT16, 2, wa,
               dims, strides, box, es,
               CU_TENSOR_MAP_INTERLEAVE_NONE, CU_TENSOR_MAP_SWIZZLE_128B,
               CU_TENSOR_MAP_L2_PROMOTION_L2_128B,
               CU_TENSOR_MAP_FLOAT_OOB_FILL_NONE);
    }
}

extern "C" void kernel_launch(void* const* d_in, const int* in_sizes, int n_in,
                              void* d_out, int out_size) {
    const float* x = (const float*)d_in[0];   // [T, B, IN]
    const float* w = (const float*)d_in[1];   // [OUT, IN]
    float* out = (float*)d_out;               // [T, B, OUT]

    build_tensormaps();

    convert_all_kernel<<<XBLKS + WBLKS, 256>>>(x, w);

    cudaFuncSetAttribute(snn_fused_kernel,
                         cudaFuncAttributeMaxDynamicSharedMemorySize, SMEM_BYTES);
    snn_fused_kernel<<<(M_TOTAL / TILE_M) * (OUT_DIM / TILE_N), NTH, SMEM_BYTES>>>(
        s_tma_a, s_tma_b, out);
}